// round 2
// baseline (speedup 1.0000x reference)
#include <cuda_runtime.h>
#include <stdint.h>

#define BATCH 4096
#define IN_F  2048
#define OUT_F 4096
#define WORDS (IN_F / 64)     // 32 u64 per row
#define B_PER_BLK 8           // batch rows per output block

// Scratch (allocation-free: __device__ globals)
__device__ uint64_t g_xbits[(size_t)BATCH * WORDS];
__device__ uint64_t g_pbits[(size_t)OUT_F * WORDS];
__device__ uint64_t g_xsig[BATCH];
__device__ uint64_t g_psig[OUT_F];

// -----------------------------------------------------------------------------
// Pack kernel: one warp per row. float4 loads (128 elements per warp-iter),
// 4 ballots per iter. Bit ordering within the packed words is a fixed
// permutation of the element order — identical for x and path rows, so
// equality of packed rows <=> equality of original bit rows. Signature is a
// multiplicative mix over the packed words (same permutation both sides).
// -----------------------------------------------------------------------------
__global__ void fsu_pack_kernel(const float* __restrict__ x,
                                const float* __restrict__ w,
                                const float* __restrict__ rng)
{
    const int gwarp = (blockIdx.x * blockDim.x + threadIdx.x) >> 5;
    const int lane  = threadIdx.x & 31;
    const bool isX  = gwarp < BATCH;
    const int row   = isX ? gwarp : (gwarp - BATCH);
    if (!isX && row >= OUT_F) return;

    const float rv = __ldg(rng);
    const float4* src = reinterpret_cast<const float4*>(
        (isX ? (x + (size_t)row * IN_F) : (w + (size_t)row * IN_F)));

    uint64_t sig = 0;
    uint64_t myword = 0;

    #pragma unroll 4
    for (int it = 0; it < IN_F / 128; ++it) {      // 16 iterations
        const float4 v = __ldg(src + it * 32 + lane);
        bool b0, b1, b2, b3;
        if (isX) {
            b0 = (v.x > 0.5f); b1 = (v.y > 0.5f);
            b2 = (v.z > 0.5f); b3 = (v.w > 0.5f);
        } else {
            // BinGen/BSGen: prob=(w+1)*0.5; source=round(prob*256); bit = source > rng
            b0 = (rintf((v.x + 1.0f) * 0.5f * 256.0f) > rv);
            b1 = (rintf((v.y + 1.0f) * 0.5f * 256.0f) > rv);
            b2 = (rintf((v.z + 1.0f) * 0.5f * 256.0f) > rv);
            b3 = (rintf((v.w + 1.0f) * 0.5f * 256.0f) > rv);
        }
        const uint32_t m0 = __ballot_sync(0xFFFFFFFFu, b0);
        const uint32_t m1 = __ballot_sync(0xFFFFFFFFu, b1);
        const uint32_t m2 = __ballot_sync(0xFFFFFFFFu, b2);
        const uint32_t m3 = __ballot_sync(0xFFFFFFFFu, b3);
        const uint64_t wa = (uint64_t)m0 | ((uint64_t)m1 << 32);
        const uint64_t wb = (uint64_t)m2 | ((uint64_t)m3 << 32);
        if (lane == 2 * it)     myword = wa;
        if (lane == 2 * it + 1) myword = wb;
        sig = sig * 0x9E3779B97F4A7C15ull + wa;
        sig = sig * 0x9E3779B97F4A7C15ull + wb;
    }

    if (isX) {
        g_xbits[(size_t)row * WORDS + lane] = myword;
        if (lane == 0) g_xsig[row] = sig;
    } else {
        g_pbits[(size_t)row * WORDS + lane] = myword;
        if (lane == 0) g_psig[row] = sig;
    }
}

// Exact fallback: full 2048-bit compare. Essentially never taken (needs a
// 64-bit signature collision), but guarantees bit-exact correctness.
__device__ __noinline__ float fsu_full_cmp(int b, int o)
{
    const uint64_t* xb = &g_xbits[(size_t)b * WORDS];
    const uint64_t* pb = &g_pbits[(size_t)o * WORDS];
    #pragma unroll 8
    for (int k = 0; k < WORDS; ++k) {
        if (__ldg(xb + k) != __ldg(pb + k)) return 0.0f;
    }
    return 1.0f;
}

// -----------------------------------------------------------------------------
// Output kernel: psigs staged in smem once per block; each block emits
// B_PER_BLK full batch rows (float4 stores). Store-stream bound.
// -----------------------------------------------------------------------------
__global__ __launch_bounds__(256) void fsu_out_kernel(float* __restrict__ out)
{
    __shared__ uint64_t s_psig[OUT_F];            // 32 KB

    for (int i = threadIdx.x; i < OUT_F; i += 256)
        s_psig[i] = g_psig[i];
    __syncthreads();

    const int bbase = blockIdx.x * B_PER_BLK;

    #pragma unroll
    for (int bb = 0; bb < B_PER_BLK; ++bb) {
        const int b = bbase + bb;
        const uint64_t xs = g_xsig[b];
        float4* outv = reinterpret_cast<float4*>(out + (size_t)b * OUT_F);

        #pragma unroll
        for (int j = threadIdx.x; j < OUT_F / 4; j += 256) {
            const int o = j * 4;
            float4 r = make_float4(0.0f, 0.0f, 0.0f, 0.0f);
            if (s_psig[o + 0] == xs) r.x = fsu_full_cmp(b, o + 0);
            if (s_psig[o + 1] == xs) r.y = fsu_full_cmp(b, o + 1);
            if (s_psig[o + 2] == xs) r.z = fsu_full_cmp(b, o + 2);
            if (s_psig[o + 3] == xs) r.w = fsu_full_cmp(b, o + 3);
            outv[j] = r;
        }
    }
}

extern "C" void kernel_launch(void* const* d_in, const int* in_sizes, int n_in,
                              void* d_out, int out_size)
{
    const float* x   = (const float*)d_in[0];
    const float* w   = (const float*)d_in[1];
    const float* rng = (const float*)d_in[2];
    float* out = (float*)d_out;

    // Pack: (BATCH + OUT_F) warps, 8 warps per block
    const int totalWarps = BATCH + OUT_F;            // 8192
    fsu_pack_kernel<<<totalWarps / 8, 256>>>(x, w, rng);

    // Output: each block handles B_PER_BLK batch rows
    fsu_out_kernel<<<BATCH / B_PER_BLK, 256>>>(out);
}

// round 3
// speedup vs baseline: 1.0478x; 1.0478x over previous
#include <cuda_runtime.h>
#include <stdint.h>

#define BATCH 4096
#define IN_F  2048
#define OUT_F 4096
#define WORDS (IN_F / 64)     // 32 u64 per row
#define HT_SIZE 16384         // power of 2, 4x oversized
#define MAX_MATCH (1 << 20)

// Scratch (allocation-free: __device__ globals)
__device__ uint64_t g_xbits[(size_t)BATCH * WORDS];
__device__ uint64_t g_pbits[(size_t)OUT_F * WORDS];
__device__ uint64_t g_xsig[BATCH];
__device__ uint64_t g_psig[OUT_F];
__device__ uint32_t g_ht[HT_SIZE];       // 0 = empty, else o+1
__device__ int      g_nmatch;
__device__ uint2    g_matches[MAX_MATCH];

__device__ __forceinline__ uint32_t hash_sig(uint64_t s)
{
    s ^= s >> 33; s *= 0xff51afd7ed558ccdULL; s ^= s >> 33;
    return (uint32_t)s & (HT_SIZE - 1);
}

// -----------------------------------------------------------------------------
// Pack: one warp per row; float4 loads, 4 ballots/iter, fully unrolled (MLP).
// Bit order within packed words is a fixed permutation, identical for x and
// path rows -> packed-row equality <=> original-bit-row equality.
// -----------------------------------------------------------------------------
__global__ void fsu_pack_kernel(const float* __restrict__ x,
                                const float* __restrict__ w,
                                const float* __restrict__ rng)
{
    const int gwarp = (blockIdx.x * blockDim.x + threadIdx.x) >> 5;
    const int lane  = threadIdx.x & 31;
    const bool isX  = gwarp < BATCH;
    const int row   = isX ? gwarp : (gwarp - BATCH);
    if (!isX && row >= OUT_F) return;

    const float rv = __ldg(rng);
    const float4* src = reinterpret_cast<const float4*>(
        (isX ? (x + (size_t)row * IN_F) : (w + (size_t)row * IN_F)));

    uint64_t sig = 0;
    uint64_t myword = 0;

    #pragma unroll
    for (int it = 0; it < IN_F / 128; ++it) {      // 16 iterations
        const float4 v = __ldg(src + it * 32 + lane);
        bool b0, b1, b2, b3;
        if (isX) {
            b0 = (v.x > 0.5f); b1 = (v.y > 0.5f);
            b2 = (v.z > 0.5f); b3 = (v.w > 0.5f);
        } else {
            // BinGen/BSGen: prob=(w+1)*0.5; source=round(prob*256); bit = source > rng
            b0 = (rintf((v.x + 1.0f) * 0.5f * 256.0f) > rv);
            b1 = (rintf((v.y + 1.0f) * 0.5f * 256.0f) > rv);
            b2 = (rintf((v.z + 1.0f) * 0.5f * 256.0f) > rv);
            b3 = (rintf((v.w + 1.0f) * 0.5f * 256.0f) > rv);
        }
        const uint32_t m0 = __ballot_sync(0xFFFFFFFFu, b0);
        const uint32_t m1 = __ballot_sync(0xFFFFFFFFu, b1);
        const uint32_t m2 = __ballot_sync(0xFFFFFFFFu, b2);
        const uint32_t m3 = __ballot_sync(0xFFFFFFFFu, b3);
        const uint64_t wa = (uint64_t)m0 | ((uint64_t)m1 << 32);
        const uint64_t wb = (uint64_t)m2 | ((uint64_t)m3 << 32);
        if (lane == 2 * it)     myword = wa;
        if (lane == 2 * it + 1) myword = wb;
        sig = sig * 0x9E3779B97F4A7C15ull + wa;
        sig = sig * 0x9E3779B97F4A7C15ull + wb;
    }

    if (isX) {
        g_xbits[(size_t)row * WORDS + lane] = myword;
        if (lane == 0) g_xsig[row] = sig;
    } else {
        g_pbits[(size_t)row * WORDS + lane] = myword;
        if (lane == 0) g_psig[row] = sig;
    }
}

// Reset hash table + match counter (deterministic per call)
__global__ void fsu_reset_kernel()
{
    const int i = blockIdx.x * blockDim.x + threadIdx.x;
    if (i < HT_SIZE) g_ht[i] = 0;
    if (i == 0) g_nmatch = 0;
}

// Insert all psigs into the open-addressing table (stores o+1)
__global__ void fsu_insert_kernel()
{
    const int o = blockIdx.x * blockDim.x + threadIdx.x;
    if (o >= OUT_F) return;
    uint32_t h = hash_sig(g_psig[o]);
    while (atomicCAS(&g_ht[h], 0u, (uint32_t)(o + 1)) != 0u)
        h = (h + 1) & (HT_SIZE - 1);
}

// Exact verification: full 2048-bit compare
__device__ bool fsu_full_cmp(int b, int o)
{
    const uint64_t* xb = &g_xbits[(size_t)b * WORDS];
    const uint64_t* pb = &g_pbits[(size_t)o * WORDS];
    #pragma unroll 8
    for (int k = 0; k < WORDS; ++k)
        if (__ldg(xb + k) != __ldg(pb + k)) return false;
    return true;
}

// Probe: each batch row walks its hash cluster; verified matches recorded.
__global__ void fsu_probe_kernel()
{
    const int b = blockIdx.x * blockDim.x + threadIdx.x;
    if (b >= BATCH) return;
    const uint64_t xs = g_xsig[b];
    uint32_t h = hash_sig(xs);
    uint32_t e;
    while ((e = g_ht[h]) != 0u) {
        const int o = (int)e - 1;
        if (g_psig[o] == xs && fsu_full_cmp(b, o)) {
            const int idx = atomicAdd(&g_nmatch, 1);
            if (idx < MAX_MATCH) g_matches[idx] = make_uint2((uint32_t)b, (uint32_t)o);
        }
        h = (h + 1) & (HT_SIZE - 1);
    }
}

// Zero-fill: pure float4 store stream
__global__ __launch_bounds__(256) void fsu_zero_kernel(float4* __restrict__ out)
{
    const int i = blockIdx.x * blockDim.x + threadIdx.x;
    const float4 z = make_float4(0.0f, 0.0f, 0.0f, 0.0f);
    const int total = (BATCH * OUT_F) / 4;          // 4M float4
    #pragma unroll
    for (int k = 0; k < 4; ++k) {
        const int idx = i + k * (gridDim.x * blockDim.x);
        if (idx < total) out[idx] = z;
    }
}

// Fixup: set the (rare) matched elements to 1.0
__global__ void fsu_fixup_kernel(float* __restrict__ out)
{
    int n = g_nmatch;
    if (n > MAX_MATCH) n = MAX_MATCH;
    for (int i = threadIdx.x; i < n; i += blockDim.x) {
        const uint2 m = g_matches[i];
        out[(size_t)m.x * OUT_F + m.y] = 1.0f;
    }
}

extern "C" void kernel_launch(void* const* d_in, const int* in_sizes, int n_in,
                              void* d_out, int out_size)
{
    const float* x   = (const float*)d_in[0];
    const float* w   = (const float*)d_in[1];
    const float* rng = (const float*)d_in[2];
    float* out = (float*)d_out;

    fsu_reset_kernel<<<HT_SIZE / 256, 256>>>();

    const int totalWarps = BATCH + OUT_F;            // 8192 warps
    fsu_pack_kernel<<<totalWarps / 8, 256>>>(x, w, rng);

    fsu_insert_kernel<<<OUT_F / 256, 256>>>();
    fsu_probe_kernel<<<BATCH / 256, 256>>>();

    const int total4 = (BATCH * OUT_F) / 4;          // 4M float4 stores
    fsu_zero_kernel<<<total4 / (256 * 4), 256>>>(reinterpret_cast<float4*>(out));

    fsu_fixup_kernel<<<1, 256>>>(out);
}